// round 12
// baseline (speedup 1.0000x reference)
#include <cuda_runtime.h>
#include <cstdint>

#define N_IN_CH   256
#define N_WDIM    512
#define N_BATCH   8

// styles[b][c], produced by kernel A, consumed by kernel B
__device__ float g_styles[N_BATCH * N_IN_CH];

// ---------------------------------------------------------------------------
// Kernel A: styles[b][c] = (dot(w[b,:], affine_W[c,:]) / sqrt(512) + affine_b[c]) / 16
// PDL: triggers completion immediately so modconv can start prefetching.
// ---------------------------------------------------------------------------
__global__ void styles_kernel(const float* __restrict__ w,
                              const float* __restrict__ affine_W,
                              const float* __restrict__ affine_b) {
    cudaTriggerProgrammaticLaunchCompletion();

    int gw   = (blockIdx.x * blockDim.x + threadIdx.x) >> 5;
    int lane = threadIdx.x & 31;
    if (gw >= N_BATCH * N_IN_CH) return;
    int b = gw >> 8;
    int c = gw & 255;

    const float* wr = w + (size_t)b * N_WDIM;
    const float* ar = affine_W + (size_t)c * N_WDIM;

    float s = 0.f;
#pragma unroll
    for (int i = 0; i < N_WDIM / 32; ++i) {
        int k = lane + 32 * i;
        s += wr[k] * ar[k];
    }
#pragma unroll
    for (int off = 16; off; off >>= 1)
        s += __shfl_xor_sync(0xffffffffu, s, off);

    if (lane == 0) {
        const float affine_gain = 0.04419417382415922f;  // 1/sqrt(512)
        const float weight_gain = 0.0625f;               // 1/sqrt(256)
        g_styles[gw] = (s * affine_gain + affine_b[c]) * weight_gain;
    }
}

// ---------------------------------------------------------------------------
// Kernel B: warp-per-point-pair, depth-2 software pipeline via TWO register
// buffers: consume A(i) -> refill A(i+2); consume B(i+1) -> refill B(i+3).
// __launch_bounds__(128, 6): regs capped at 85 -> 24 warps/SM.
// ---------------------------------------------------------------------------
__global__ void __launch_bounds__(128, 6)
modconv_kernel(const float4* __restrict__ xf,      // (n, 64) float4 view of (n,256)
               const int*    __restrict__ coord,   // (n, 4), col 0 = batch idx
               const float*  __restrict__ convW,   // (256, 3)
               const float*  __restrict__ convb,   // (3,)
               float*        __restrict__ out,     // (n, 3)
               int n) {
    __shared__ float s_style[N_BATCH * N_IN_CH];   // 8 KB

    int lane = threadIdx.x & 31;
    bool lo  = (lane < 16);

    // conv_W / conv_b are kernel inputs: safe before the PDL grid sync.
    float wreg[8][3];
#pragma unroll
    for (int j = 0; j < 8; ++j) {
        int c = (j < 4) ? (lane * 4 + j) : (128 + lane * 4 + (j - 4));
        wreg[j][0] = convW[c * 3 + 0];
        wreg[j][1] = convW[c * 3 + 1];
        wreg[j][2] = convW[c * 3 + 2];
    }
    float bb0 = convb[0], bb1 = convb[1], bb2 = convb[2];

    int warp   = (blockIdx.x * blockDim.x + threadIdx.x) >> 5;
    int nwarps = (gridDim.x * blockDim.x) >> 5;
    int stride = nwarps * 2;

    int p = warp * 2;

    // Two payload buffers
    int    Ab0, Ab1;  float4 Axa0, Axb0, Axa1, Axb1;
    int    Bb0, Bb1;  float4 Bxa0, Bxb0, Bxa1, Bxb1;

#define PF(BUF, P)                                                          \
    do {                                                                    \
        int q0 = (P); if (q0 >= n) q0 = n - 1;                              \
        int q1 = q0 + 1; if (q1 >= n) q1 = n - 1;                           \
        BUF##b0 = __ldg(coord + (size_t)q0 * 4);                            \
        BUF##b1 = __ldg(coord + (size_t)q1 * 4);                            \
        const float4* r0 = xf + (size_t)q0 * 64;                            \
        const float4* r1 = xf + (size_t)q1 * 64;                            \
        BUF##xa0 = __ldcs(r0 + lane);                                       \
        BUF##xb0 = __ldcs(r0 + lane + 32);                                  \
        BUF##xa1 = __ldcs(r1 + lane);                                       \
        BUF##xb1 = __ldcs(r1 + lane + 32);                                  \
    } while (0)

    // x / coord are kernel inputs: prefetch BEFORE waiting on styles_kernel.
    if (p < n) {
        PF(A, p);
        PF(B, p + stride);   // PF clamps internally
    }

    // Wait for styles_kernel completion (+ visibility), then stage styles.
    cudaGridDependencySynchronize();

    for (int i = threadIdx.x; i < N_BATCH * N_IN_CH; i += blockDim.x)
        s_style[i] = g_styles[i];
    __syncthreads();

    if (p >= n) return;

#define ACC3(m, j, A0, A1, A2)        \
    do {                              \
        A0 += (m) * wreg[j][0];       \
        A1 += (m) * wreg[j][1];       \
        A2 += (m) * wreg[j][2];       \
    } while (0)

#define STEP(BUF)                                                           \
    do {                                                                    \
        const float* st0 = s_style + BUF##b0 * N_IN_CH;                     \
        const float* st1 = s_style + BUF##b1 * N_IN_CH;                     \
        float a00 = 0.f, a01 = 0.f, a02 = 0.f;                              \
        float a10 = 0.f, a11 = 0.f, a12 = 0.f;                              \
        float m; float4 s;                                                  \
        s = *(const float4*)(st0 + lane * 4);                               \
        m = BUF##xa0.x * s.x; ACC3(m, 0, a00, a01, a02);                    \
        m = BUF##xa0.y * s.y; ACC3(m, 1, a00, a01, a02);                    \
        m = BUF##xa0.z * s.z; ACC3(m, 2, a00, a01, a02);                    \
        m = BUF##xa0.w * s.w; ACC3(m, 3, a00, a01, a02);                    \
        s = *(const float4*)(st0 + 128 + lane * 4);                         \
        m = BUF##xb0.x * s.x; ACC3(m, 4, a00, a01, a02);                    \
        m = BUF##xb0.y * s.y; ACC3(m, 5, a00, a01, a02);                    \
        m = BUF##xb0.z * s.z; ACC3(m, 6, a00, a01, a02);                    \
        m = BUF##xb0.w * s.w; ACC3(m, 7, a00, a01, a02);                    \
        s = *(const float4*)(st1 + lane * 4);                               \
        m = BUF##xa1.x * s.x; ACC3(m, 0, a10, a11, a12);                    \
        m = BUF##xa1.y * s.y; ACC3(m, 1, a10, a11, a12);                    \
        m = BUF##xa1.z * s.z; ACC3(m, 2, a10, a11, a12);                    \
        m = BUF##xa1.w * s.w; ACC3(m, 3, a10, a11, a12);                    \
        s = *(const float4*)(st1 + 128 + lane * 4);                         \
        m = BUF##xb1.x * s.x; ACC3(m, 4, a10, a11, a12);                    \
        m = BUF##xb1.y * s.y; ACC3(m, 5, a10, a11, a12);                    \
        m = BUF##xb1.z * s.z; ACC3(m, 6, a10, a11, a12);                    \
        m = BUF##xb1.w * s.w; ACC3(m, 7, a10, a11, a12);                    \
        if (p + 2 * stride < n) PF(BUF, p + 2 * stride);                    \
        float v0 = lo ? a00 : a10;                                          \
        float v1 = lo ? a01 : a11;                                          \
        float v2 = lo ? a02 : a12;                                          \
        float y0 = lo ? a10 : a00;                                          \
        float y1 = lo ? a11 : a01;                                          \
        float y2 = lo ? a12 : a02;                                          \
        v0 += __shfl_xor_sync(0xffffffffu, y0, 16);                         \
        v1 += __shfl_xor_sync(0xffffffffu, y1, 16);                         \
        v2 += __shfl_xor_sync(0xffffffffu, y2, 16);                         \
        _Pragma("unroll")                                                   \
        for (int off = 8; off; off >>= 1) {                                 \
            v0 += __shfl_xor_sync(0xffffffffu, v0, off);                    \
            v1 += __shfl_xor_sync(0xffffffffu, v1, off);                    \
            v2 += __shfl_xor_sync(0xffffffffu, v2, off);                    \
        }                                                                   \
        if (lane == 0) {                                                    \
            float* o = out + (size_t)p * 3;                                 \
            o[0] = fminf(fmaxf(v0 + bb0, -256.f), 256.f);                   \
            o[1] = fminf(fmaxf(v1 + bb1, -256.f), 256.f);                   \
            o[2] = fminf(fmaxf(v2 + bb2, -256.f), 256.f);                   \
        } else if (lane == 16 && (p + 1 < n)) {                             \
            float* o = out + (size_t)(p + 1) * 3;                           \
            o[0] = fminf(fmaxf(v0 + bb0, -256.f), 256.f);                   \
            o[1] = fminf(fmaxf(v1 + bb1, -256.f), 256.f);                   \
            o[2] = fminf(fmaxf(v2 + bb2, -256.f), 256.f);                   \
        }                                                                   \
        p += stride;                                                        \
    } while (0)

    while (true) {
        STEP(A);         // consumes i, refills A for i+2
        if (p >= n) break;
        STEP(B);         // consumes i+1, refills B for i+3
        if (p >= n) break;
    }

#undef STEP
#undef ACC3
#undef PF
}

// ---------------------------------------------------------------------------
// kernel_launch
// inputs (metadata order): x_feat, x_coord, w, affine_W, affine_b, conv_W, conv_b
// ---------------------------------------------------------------------------
extern "C" void kernel_launch(void* const* d_in, const int* in_sizes, int n_in,
                              void* d_out, int out_size) {
    const float* x_feat   = (const float*)d_in[0];
    const int*   x_coord  = (const int*)  d_in[1];
    const float* w        = (const float*)d_in[2];
    const float* affine_W = (const float*)d_in[3];
    const float* affine_b = (const float*)d_in[4];
    const float* conv_W   = (const float*)d_in[5];
    const float* conv_b   = (const float*)d_in[6];
    float* out = (float*)d_out;

    int n = in_sizes[0] / N_IN_CH;

    // Primary: styles (PDL trigger at entry)
    styles_kernel<<<256, 256>>>(w, affine_W, affine_b);

    // Secondary: modconv; starts early, syncs on g_styles internally.
    cudaLaunchConfig_t cfg = {};
    cfg.gridDim  = dim3(148 * 6, 1, 1);   // 6 blocks/SM (reg-capped at 85)
    cfg.blockDim = dim3(128, 1, 1);
    cfg.dynamicSmemBytes = 0;

    cudaLaunchAttribute attrs[1];
    attrs[0].id = cudaLaunchAttributeProgrammaticStreamSerialization;
    attrs[0].val.programmaticStreamSerializationAllowed = 1;
    cfg.attrs    = attrs;
    cfg.numAttrs = 1;

    cudaLaunchKernelEx(&cfg, modconv_kernel,
                       (const float4*)x_feat, x_coord, conv_W, conv_b, out, n);
}

// round 13
// speedup vs baseline: 1.1595x; 1.1595x over previous
#include <cuda_runtime.h>
#include <cstdint>

#define N_IN_CH   256
#define N_WDIM    512
#define N_BATCH   8

// styles[b][c], produced by kernel A, consumed by kernel B
__device__ float g_styles[N_BATCH * N_IN_CH];

// ---------------------------------------------------------------------------
// Kernel A: styles[b][c] = (dot(w[b,:], affine_W[c,:]) / sqrt(512) + affine_b[c]) / 16
// PDL: triggers completion immediately so modconv can start prefetching.
// ---------------------------------------------------------------------------
__global__ void styles_kernel(const float* __restrict__ w,
                              const float* __restrict__ affine_W,
                              const float* __restrict__ affine_b) {
    cudaTriggerProgrammaticLaunchCompletion();

    int gw   = (blockIdx.x * blockDim.x + threadIdx.x) >> 5;
    int lane = threadIdx.x & 31;
    if (gw >= N_BATCH * N_IN_CH) return;
    int b = gw >> 8;
    int c = gw & 255;

    const float* wr = w + (size_t)b * N_WDIM;
    const float* ar = affine_W + (size_t)c * N_WDIM;

    float s = 0.f;
#pragma unroll
    for (int i = 0; i < N_WDIM / 32; ++i) {
        int k = lane + 32 * i;
        s += wr[k] * ar[k];
    }
#pragma unroll
    for (int off = 16; off; off >>= 1)
        s += __shfl_xor_sync(0xffffffffu, s, off);

    if (lane == 0) {
        const float affine_gain = 0.04419417382415922f;  // 1/sqrt(512)
        const float weight_gain = 0.0625f;               // 1/sqrt(256)
        g_styles[gw] = (s * affine_gain + affine_b[c]) * weight_gain;
    }
}

// ---------------------------------------------------------------------------
// Kernel B: warp-per-point-pair, depth-2 register pipeline, CONTIGUOUS
// per-warp chunks: warp w owns points [w*C, w*C + C) so successive
// iterations stream adjacent 2KB blocks (DRAM row locality; coords L1-hit).
// No reg cap (R12 showed capping de-overlaps the pipeline).
// ---------------------------------------------------------------------------
__global__ void __launch_bounds__(128)
modconv_kernel(const float4* __restrict__ xf,      // (n, 64) float4 view of (n,256)
               const int*    __restrict__ coord,   // (n, 4), col 0 = batch idx
               const float*  __restrict__ convW,   // (256, 3)
               const float*  __restrict__ convb,   // (3,)
               float*        __restrict__ out,     // (n, 3)
               int n) {
    __shared__ float s_style[N_BATCH * N_IN_CH];   // 8 KB

    int lane = threadIdx.x & 31;
    bool lo  = (lane < 16);

    // conv_W / conv_b are kernel inputs: safe before the PDL grid sync.
    float wreg[8][3];
#pragma unroll
    for (int j = 0; j < 8; ++j) {
        int c = (j < 4) ? (lane * 4 + j) : (128 + lane * 4 + (j - 4));
        wreg[j][0] = convW[c * 3 + 0];
        wreg[j][1] = convW[c * 3 + 1];
        wreg[j][2] = convW[c * 3 + 2];
    }
    float bb0 = convb[0], bb1 = convb[1], bb2 = convb[2];

    int warp   = (blockIdx.x * blockDim.x + threadIdx.x) >> 5;
    int nwarps = (gridDim.x * blockDim.x) >> 5;

    // even-sized contiguous chunk per warp
    int C    = (((n + nwarps - 1) / nwarps) + 1) & ~1;
    int base = warp * C;
    int end  = base + C; if (end > n) end = n;

    int p = base;

    // Two payload buffers
    int    Ab0, Ab1;  float4 Axa0, Axb0, Axa1, Axb1;
    int    Bb0, Bb1;  float4 Bxa0, Bxb0, Bxa1, Bxb1;

#define PF(BUF, P)                                                          \
    do {                                                                    \
        int q0 = (P); if (q0 >= n) q0 = n - 1; if (q0 < 0) q0 = 0;          \
        int q1 = q0 + 1; if (q1 >= n) q1 = n - 1;                           \
        BUF##b0 = __ldg(coord + (size_t)q0 * 4);                            \
        BUF##b1 = __ldg(coord + (size_t)q1 * 4);                            \
        const float4* r0 = xf + (size_t)q0 * 64;                            \
        const float4* r1 = xf + (size_t)q1 * 64;                            \
        BUF##xa0 = __ldcs(r0 + lane);                                       \
        BUF##xb0 = __ldcs(r0 + lane + 32);                                  \
        BUF##xa1 = __ldcs(r1 + lane);                                       \
        BUF##xb1 = __ldcs(r1 + lane + 32);                                  \
    } while (0)

    // x / coord are kernel inputs: prefetch BEFORE waiting on styles_kernel.
    if (p < end) {
        PF(A, p);
        PF(B, p + 2);    // PF clamps internally
    }

    // Wait for styles_kernel completion (+ visibility), then stage styles.
    cudaGridDependencySynchronize();

    for (int i = threadIdx.x; i < N_BATCH * N_IN_CH; i += blockDim.x)
        s_style[i] = g_styles[i];
    __syncthreads();

    if (p >= end) return;

#define ACC3(m, j, A0, A1, A2)        \
    do {                              \
        A0 += (m) * wreg[j][0];       \
        A1 += (m) * wreg[j][1];       \
        A2 += (m) * wreg[j][2];       \
    } while (0)

#define STEP(BUF)                                                           \
    do {                                                                    \
        const float* st0 = s_style + BUF##b0 * N_IN_CH;                     \
        const float* st1 = s_style + BUF##b1 * N_IN_CH;                     \
        float a00 = 0.f, a01 = 0.f, a02 = 0.f;                              \
        float a10 = 0.f, a11 = 0.f, a12 = 0.f;                              \
        float m; float4 s;                                                  \
        s = *(const float4*)(st0 + lane * 4);                               \
        m = BUF##xa0.x * s.x; ACC3(m, 0, a00, a01, a02);                    \
        m = BUF##xa0.y * s.y; ACC3(m, 1, a00, a01, a02);                    \
        m = BUF##xa0.z * s.z; ACC3(m, 2, a00, a01, a02);                    \
        m = BUF##xa0.w * s.w; ACC3(m, 3, a00, a01, a02);                    \
        s = *(const float4*)(st0 + 128 + lane * 4);                         \
        m = BUF##xb0.x * s.x; ACC3(m, 4, a00, a01, a02);                    \
        m = BUF##xb0.y * s.y; ACC3(m, 5, a00, a01, a02);                    \
        m = BUF##xb0.z * s.z; ACC3(m, 6, a00, a01, a02);                    \
        m = BUF##xb0.w * s.w; ACC3(m, 7, a00, a01, a02);                    \
        s = *(const float4*)(st1 + lane * 4);                               \
        m = BUF##xa1.x * s.x; ACC3(m, 0, a10, a11, a12);                    \
        m = BUF##xa1.y * s.y; ACC3(m, 1, a10, a11, a12);                    \
        m = BUF##xa1.z * s.z; ACC3(m, 2, a10, a11, a12);                    \
        m = BUF##xa1.w * s.w; ACC3(m, 3, a10, a11, a12);                    \
        s = *(const float4*)(st1 + 128 + lane * 4);                         \
        m = BUF##xb1.x * s.x; ACC3(m, 4, a10, a11, a12);                    \
        m = BUF##xb1.y * s.y; ACC3(m, 5, a10, a11, a12);                    \
        m = BUF##xb1.z * s.z; ACC3(m, 6, a10, a11, a12);                    \
        m = BUF##xb1.w * s.w; ACC3(m, 7, a10, a11, a12);                    \
        if (p + 4 < end) PF(BUF, p + 4);                                    \
        float v0 = lo ? a00 : a10;                                          \
        float v1 = lo ? a01 : a11;                                          \
        float v2 = lo ? a02 : a12;                                          \
        float y0 = lo ? a10 : a00;                                          \
        float y1 = lo ? a11 : a01;                                          \
        float y2 = lo ? a12 : a02;                                          \
        v0 += __shfl_xor_sync(0xffffffffu, y0, 16);                         \
        v1 += __shfl_xor_sync(0xffffffffu, y1, 16);                         \
        v2 += __shfl_xor_sync(0xffffffffu, y2, 16);                         \
        _Pragma("unroll")                                                   \
        for (int off = 8; off; off >>= 1) {                                 \
            v0 += __shfl_xor_sync(0xffffffffu, v0, off);                    \
            v1 += __shfl_xor_sync(0xffffffffu, v1, off);                    \
            v2 += __shfl_xor_sync(0xffffffffu, v2, off);                    \
        }                                                                   \
        if (lane == 0) {                                                    \
            float* o = out + (size_t)p * 3;                                 \
            o[0] = fminf(fmaxf(v0 + bb0, -256.f), 256.f);                   \
            o[1] = fminf(fmaxf(v1 + bb1, -256.f), 256.f);                   \
            o[2] = fminf(fmaxf(v2 + bb2, -256.f), 256.f);                   \
        } else if (lane == 16 && (p + 1 < n)) {                             \
            float* o = out + (size_t)(p + 1) * 3;                           \
            o[0] = fminf(fmaxf(v0 + bb0, -256.f), 256.f);                   \
            o[1] = fminf(fmaxf(v1 + bb1, -256.f), 256.f);                   \
            o[2] = fminf(fmaxf(v2 + bb2, -256.f), 256.f);                   \
        }                                                                   \
        p += 2;                                                             \
    } while (0)

    while (true) {
        STEP(A);         // consumes pair p, refills A for p+4
        if (p >= end) break;
        STEP(B);         // consumes pair p, refills B for p+4
        if (p >= end) break;
    }

#undef STEP
#undef ACC3
#undef PF
}

// ---------------------------------------------------------------------------
// kernel_launch
// inputs (metadata order): x_feat, x_coord, w, affine_W, affine_b, conv_W, conv_b
// ---------------------------------------------------------------------------
extern "C" void kernel_launch(void* const* d_in, const int* in_sizes, int n_in,
                              void* d_out, int out_size) {
    const float* x_feat   = (const float*)d_in[0];
    const int*   x_coord  = (const int*)  d_in[1];
    const float* w        = (const float*)d_in[2];
    const float* affine_W = (const float*)d_in[3];
    const float* affine_b = (const float*)d_in[4];
    const float* conv_W   = (const float*)d_in[5];
    const float* conv_b   = (const float*)d_in[6];
    float* out = (float*)d_out;

    int n = in_sizes[0] / N_IN_CH;

    // Primary: styles (PDL trigger at entry)
    styles_kernel<<<256, 256>>>(w, affine_W, affine_b);

    // Secondary: modconv; starts early, syncs on g_styles internally.
    cudaLaunchConfig_t cfg = {};
    cfg.gridDim  = dim3(148 * 5, 1, 1);   // 5 blocks/SM (96 regs, like R9)
    cfg.blockDim = dim3(128, 1, 1);
    cfg.dynamicSmemBytes = 0;

    cudaLaunchAttribute attrs[1];
    attrs[0].id = cudaLaunchAttributeProgrammaticStreamSerialization;
    attrs[0].val.programmaticStreamSerializationAllowed = 1;
    cfg.attrs    = attrs;
    cfg.numAttrs = 1;

    cudaLaunchKernelEx(&cfg, modconv_kernel,
                       (const float4*)x_feat, x_coord, conv_W, conv_b, out, n);
}

// round 14
// speedup vs baseline: 1.2383x; 1.0679x over previous
#include <cuda_runtime.h>
#include <cstdint>

#define N_IN_CH   256
#define N_WDIM    512
#define N_BATCH   8

// styles[b][c], produced by kernel A, consumed by kernel B
__device__ float g_styles[N_BATCH * N_IN_CH];

// ---------------------------------------------------------------------------
// Kernel A: styles[b][c] = (dot(w[b,:], affine_W[c,:]) / sqrt(512) + affine_b[c]) / 16
// PDL: triggers completion immediately so modconv can start prefetching.
// ---------------------------------------------------------------------------
__global__ void styles_kernel(const float* __restrict__ w,
                              const float* __restrict__ affine_W,
                              const float* __restrict__ affine_b) {
    cudaTriggerProgrammaticLaunchCompletion();

    int gw   = (blockIdx.x * blockDim.x + threadIdx.x) >> 5;
    int lane = threadIdx.x & 31;
    if (gw >= N_BATCH * N_IN_CH) return;
    int b = gw >> 8;
    int c = gw & 255;

    const float* wr = w + (size_t)b * N_WDIM;
    const float* ar = affine_W + (size_t)c * N_WDIM;

    float s = 0.f;
#pragma unroll
    for (int i = 0; i < N_WDIM / 32; ++i) {
        int k = lane + 32 * i;
        s += wr[k] * ar[k];
    }
#pragma unroll
    for (int off = 16; off; off >>= 1)
        s += __shfl_xor_sync(0xffffffffu, s, off);

    if (lane == 0) {
        const float affine_gain = 0.04419417382415922f;  // 1/sqrt(512)
        const float weight_gain = 0.0625f;               // 1/sqrt(256)
        g_styles[gw] = (s * affine_gain + affine_b[c]) * weight_gain;
    }
}

// ---------------------------------------------------------------------------
// Kernel B: warp-per-point-pair, depth-2 software pipeline via TWO register
// buffers: consume A(i) -> refill A(i+2); consume B(i+1) -> refill B(i+3).
// Stride mapping across warps (chip-wide interleave). No reg cap.
// Prologue: wreg + x prefetches issue BEFORE the PDL grid-dependency sync.
// ---------------------------------------------------------------------------
__global__ void __launch_bounds__(128)
modconv_kernel(const float4* __restrict__ xf,      // (n, 64) float4 view of (n,256)
               const int*    __restrict__ coord,   // (n, 4), col 0 = batch idx
               const float*  __restrict__ convW,   // (256, 3)
               const float*  __restrict__ convb,   // (3,)
               float*        __restrict__ out,     // (n, 3)
               int n) {
    __shared__ float s_style[N_BATCH * N_IN_CH];   // 8 KB

    int lane = threadIdx.x & 31;
    bool lo  = (lane < 16);

    // conv_W / conv_b are kernel inputs: safe before the PDL grid sync.
    float wreg[8][3];
#pragma unroll
    for (int j = 0; j < 8; ++j) {
        int c = (j < 4) ? (lane * 4 + j) : (128 + lane * 4 + (j - 4));
        wreg[j][0] = convW[c * 3 + 0];
        wreg[j][1] = convW[c * 3 + 1];
        wreg[j][2] = convW[c * 3 + 2];
    }
    float bb0 = convb[0], bb1 = convb[1], bb2 = convb[2];

    int warp   = (blockIdx.x * blockDim.x + threadIdx.x) >> 5;
    int nwarps = (gridDim.x * blockDim.x) >> 5;
    int stride = nwarps * 2;

    int p = warp * 2;

    // Two payload buffers
    int    Ab0, Ab1;  float4 Axa0, Axb0, Axa1, Axb1;
    int    Bb0, Bb1;  float4 Bxa0, Bxb0, Bxa1, Bxb1;

#define PF(BUF, P)                                                          \
    do {                                                                    \
        int q0 = (P); if (q0 >= n) q0 = n - 1;                              \
        int q1 = q0 + 1; if (q1 >= n) q1 = n - 1;                           \
        BUF##b0 = __ldg(coord + (size_t)q0 * 4);                            \
        BUF##b1 = __ldg(coord + (size_t)q1 * 4);                            \
        const float4* r0 = xf + (size_t)q0 * 64;                            \
        const float4* r1 = xf + (size_t)q1 * 64;                            \
        BUF##xa0 = __ldcs(r0 + lane);                                       \
        BUF##xb0 = __ldcs(r0 + lane + 32);                                  \
        BUF##xa1 = __ldcs(r1 + lane);                                       \
        BUF##xb1 = __ldcs(r1 + lane + 32);                                  \
    } while (0)

    // x / coord are kernel inputs: prefetch BEFORE waiting on styles_kernel.
    if (p < n) {
        PF(A, p);
        PF(B, p + stride);   // PF clamps internally
    }

    // Wait for styles_kernel completion (+ memory visibility), then stage styles.
    cudaGridDependencySynchronize();

    for (int i = threadIdx.x; i < N_BATCH * N_IN_CH; i += blockDim.x)
        s_style[i] = g_styles[i];
    __syncthreads();

    if (p >= n) return;

#define ACC3(m, j, A0, A1, A2)        \
    do {                              \
        A0 += (m) * wreg[j][0];       \
        A1 += (m) * wreg[j][1];       \
        A2 += (m) * wreg[j][2];       \
    } while (0)

#define STEP(BUF)                                                           \
    do {                                                                    \
        const float* st0 = s_style + BUF##b0 * N_IN_CH;                     \
        const float* st1 = s_style + BUF##b1 * N_IN_CH;                     \
        float a00 = 0.f, a01 = 0.f, a02 = 0.f;                              \
        float a10 = 0.f, a11 = 0.f, a12 = 0.f;                              \
        float m; float4 s;                                                  \
        s = *(const float4*)(st0 + lane * 4);                               \
        m = BUF##xa0.x * s.x; ACC3(m, 0, a00, a01, a02);                    \
        m = BUF##xa0.y * s.y; ACC3(m, 1, a00, a01, a02);                    \
        m = BUF##xa0.z * s.z; ACC3(m, 2, a00, a01, a02);                    \
        m = BUF##xa0.w * s.w; ACC3(m, 3, a00, a01, a02);                    \
        s = *(const float4*)(st0 + 128 + lane * 4);                         \
        m = BUF##xb0.x * s.x; ACC3(m, 4, a00, a01, a02);                    \
        m = BUF##xb0.y * s.y; ACC3(m, 5, a00, a01, a02);                    \
        m = BUF##xb0.z * s.z; ACC3(m, 6, a00, a01, a02);                    \
        m = BUF##xb0.w * s.w; ACC3(m, 7, a00, a01, a02);                    \
        s = *(const float4*)(st1 + lane * 4);                               \
        m = BUF##xa1.x * s.x; ACC3(m, 0, a10, a11, a12);                    \
        m = BUF##xa1.y * s.y; ACC3(m, 1, a10, a11, a12);                    \
        m = BUF##xa1.z * s.z; ACC3(m, 2, a10, a11, a12);                    \
        m = BUF##xa1.w * s.w; ACC3(m, 3, a10, a11, a12);                    \
        s = *(const float4*)(st1 + 128 + lane * 4);                         \
        m = BUF##xb1.x * s.x; ACC3(m, 4, a10, a11, a12);                    \
        m = BUF##xb1.y * s.y; ACC3(m, 5, a10, a11, a12);                    \
        m = BUF##xb1.z * s.z; ACC3(m, 6, a10, a11, a12);                    \
        m = BUF##xb1.w * s.w; ACC3(m, 7, a10, a11, a12);                    \
        if (p + 2 * stride < n) PF(BUF, p + 2 * stride);                    \
        float v0 = lo ? a00 : a10;                                          \
        float v1 = lo ? a01 : a11;                                          \
        float v2 = lo ? a02 : a12;                                          \
        float y0 = lo ? a10 : a00;                                          \
        float y1 = lo ? a11 : a01;                                          \
        float y2 = lo ? a12 : a02;                                          \
        v0 += __shfl_xor_sync(0xffffffffu, y0, 16);                         \
        v1 += __shfl_xor_sync(0xffffffffu, y1, 16);                         \
        v2 += __shfl_xor_sync(0xffffffffu, y2, 16);                         \
        _Pragma("unroll")                                                   \
        for (int off = 8; off; off >>= 1) {                                 \
            v0 += __shfl_xor_sync(0xffffffffu, v0, off);                    \
            v1 += __shfl_xor_sync(0xffffffffu, v1, off);                    \
            v2 += __shfl_xor_sync(0xffffffffu, v2, off);                    \
        }                                                                   \
        if (lane == 0) {                                                    \
            float* o = out + (size_t)p * 3;                                 \
            o[0] = fminf(fmaxf(v0 + bb0, -256.f), 256.f);                   \
            o[1] = fminf(fmaxf(v1 + bb1, -256.f), 256.f);                   \
            o[2] = fminf(fmaxf(v2 + bb2, -256.f), 256.f);                   \
        } else if (lane == 16 && (p + 1 < n)) {                             \
            float* o = out + (size_t)(p + 1) * 3;                           \
            o[0] = fminf(fmaxf(v0 + bb0, -256.f), 256.f);                   \
            o[1] = fminf(fmaxf(v1 + bb1, -256.f), 256.f);                   \
            o[2] = fminf(fmaxf(v2 + bb2, -256.f), 256.f);                   \
        }                                                                   \
        p += stride;                                                        \
    } while (0)

    while (true) {
        STEP(A);         // consumes i, refills A for i+2
        if (p >= n) break;
        STEP(B);         // consumes i+1, refills B for i+3
        if (p >= n) break;
    }

#undef STEP
#undef ACC3
#undef PF
}

// ---------------------------------------------------------------------------
// kernel_launch
// inputs (metadata order): x_feat, x_coord, w, affine_W, affine_b, conv_W, conv_b
// ---------------------------------------------------------------------------
extern "C" void kernel_launch(void* const* d_in, const int* in_sizes, int n_in,
                              void* d_out, int out_size) {
    const float* x_feat   = (const float*)d_in[0];
    const int*   x_coord  = (const int*)  d_in[1];
    const float* w        = (const float*)d_in[2];
    const float* affine_W = (const float*)d_in[3];
    const float* affine_b = (const float*)d_in[4];
    const float* conv_W   = (const float*)d_in[5];
    const float* conv_b   = (const float*)d_in[6];
    float* out = (float*)d_out;

    int n = in_sizes[0] / N_IN_CH;

    // Primary: styles (PDL trigger at entry)
    styles_kernel<<<256, 256>>>(w, affine_W, affine_b);

    // Secondary: modconv; starts early, syncs on g_styles internally.
    cudaLaunchConfig_t cfg = {};
    cfg.gridDim  = dim3(148 * 5, 1, 1);
    cfg.blockDim = dim3(128, 1, 1);
    cfg.dynamicSmemBytes = 0;

    cudaLaunchAttribute attrs[1];
    attrs[0].id = cudaLaunchAttributeProgrammaticStreamSerialization;
    attrs[0].val.programmaticStreamSerializationAllowed = 1;
    cfg.attrs    = attrs;
    cfg.numAttrs = 1;

    cudaLaunchKernelEx(&cfg, modconv_kernel,
                       (const float4*)x_feat, x_coord, conv_W, conv_b, out, n);
}